// round 16
// baseline (speedup 1.0000x reference)
#include <cuda_runtime.h>

// TensorProductLayer, smem-staged split-tile, 512 pairs/CTA:
//  - two 256-pair half-tiles, each its own cp.async group (depth-2 pipeline)
//  - compute+store of half 0 overlaps arrival of half 1 (wait_group 1 -> 0)
//  - all 256 threads compute in each half (1 pair/thread/half)
//  - doubled store bursts (832 f4 per half) to cut DRAM read/write turnarounds
//  - per-thread scalar compute from smem (strides 1,3,9 coprime to 32)
//  - cooperative STG.128 stores; all indexing 32-bit
// Per pair: a=x0, b=y0, u=x1(3), v=y1(3), A=x2(9), B=y2(9)
//   out0      = a*b + u.v + <A,B>_F
//   out1[i]   = a*v[i] + b*u[i] + (u^T B)[i] + (A v)[i]
//   out2[i,j] = a*B[i,j] + b*A[i,j] + u[i]*v[j] + (A B)[i,j]

#define TPB 256       // threads per block
#define PT  256       // pairs per half-tile
#define BUF_F4 1664   // f4 per half-tile buffer (256 pairs x 26 floats)
// per-buffer f4 offsets:    sa 0, sb 64,  su 128, sv 320,  sA 512,  sB 1088
// per-buffer float offsets: sa 0, sb 256, su 512, sv 1280, sA 2048, sB 4352

__device__ __forceinline__ void cp16(float4* smem_dst, const float4* gmem_src)
{
    unsigned saddr = (unsigned)__cvta_generic_to_shared(smem_dst);
    asm volatile("cp.async.cg.shared.global [%0], [%1], 16;"
                 :: "r"(saddr), "l"(gmem_src));
}

__device__ __forceinline__ void tp_pair(
    float a, float b,
    const float* __restrict__ u, const float* __restrict__ v,
    const float* __restrict__ A, const float* __restrict__ B,
    float* __restrict__ r0, float* __restrict__ r1, float* __restrict__ r2)
{
    float s0 = a * b;
#pragma unroll
    for (int i = 0; i < 3; ++i) s0 = fmaf(u[i], v[i], s0);
#pragma unroll
    for (int i = 0; i < 9; ++i) s0 = fmaf(A[i], B[i], s0);
    *r0 = s0;

#pragma unroll
    for (int i = 0; i < 3; ++i) {
        float t = a * v[i];
        t = fmaf(b, u[i], t);
#pragma unroll
        for (int d = 0; d < 3; ++d) t = fmaf(u[d], B[d * 3 + i], t);
#pragma unroll
        for (int e = 0; e < 3; ++e) t = fmaf(A[i * 3 + e], v[e], t);
        r1[i] = t;
    }

#pragma unroll
    for (int i = 0; i < 3; ++i) {
#pragma unroll
        for (int j = 0; j < 3; ++j) {
            float t = a * B[i * 3 + j];
            t = fmaf(b, A[i * 3 + j], t);
            t = fmaf(u[i], v[j], t);
#pragma unroll
            for (int e = 0; e < 3; ++e) t = fmaf(A[i * 3 + e], B[e * 3 + j], t);
            r2[i * 3 + j] = t;
        }
    }
}

// Stage one 256-pair half-tile (1664 f4) into buf over 256 threads (7 passes).
// g = f4 index of half-tile start in rank-0 space.
__device__ __forceinline__ void stage_half(
    float4* buf, int g, int tid,
    const float4* __restrict__ x0, const float4* __restrict__ y0,
    const float4* __restrict__ x1, const float4* __restrict__ y1,
    const float4* __restrict__ x2, const float4* __restrict__ y2)
{
    const int g3 = g * 3, g9 = g * 9;
#pragma unroll
    for (int k = 0; k < 7; ++k) {
        int i = tid + 256 * k;
        if (i < BUF_F4) {
            const float4* src;
            if (i < 64)        src = x0 + (g  + i);
            else if (i < 128)  src = y0 + (g  + i - 64);
            else if (i < 320)  src = x1 + (g3 + i - 128);
            else if (i < 512)  src = y1 + (g3 + i - 320);
            else if (i < 1088) src = x2 + (g9 + i - 512);
            else               src = y2 + (g9 + i - 1088);
            cp16(buf + i, src);
        }
    }
}

// Compute 256 pairs in place (all 256 threads, 1 pair each).
__device__ __forceinline__ void compute_half(float4* buf, int tid)
{
    float* f = reinterpret_cast<float*>(buf);
    float a = f[tid], b = f[256 + tid];
    float u[3], v[3], A[9], B[9];
#pragma unroll
    for (int i = 0; i < 3; ++i) { u[i] = f[512 + tid * 3 + i]; v[i] = f[1280 + tid * 3 + i]; }
#pragma unroll
    for (int i = 0; i < 9; ++i) { A[i] = f[2048 + tid * 9 + i]; B[i] = f[4352 + tid * 9 + i]; }

    float r0, r1[3], r2[9];
    tp_pair(a, b, u, v, A, B, &r0, r1, r2);

    f[tid] = r0;
#pragma unroll
    for (int i = 0; i < 3; ++i) f[512 + tid * 3 + i] = r1[i];
#pragma unroll
    for (int i = 0; i < 9; ++i) f[2048 + tid * 9 + i] = r2[i];
}

// Store results of one half-tile (832 f4) over 256 threads (4 passes).
// r0 in buf f4[0..64), r1 in f4[128..320), r2 in f4[512..1088).
__device__ __forceinline__ void store_half(
    const float4* buf, int g, int tid,
    float4* __restrict__ o0, float4* __restrict__ o1, float4* __restrict__ o2)
{
    const int g3 = g * 3, g9 = g * 9;
#pragma unroll
    for (int k = 0; k < 4; ++k) {
        int i = tid + 256 * k;
        if (i < 832) {
            if (i < 64)       __stcs(o0 + (g  + i),       buf[i]);
            else if (i < 256) __stcs(o1 + (g3 + i - 64),  buf[128 + (i - 64)]);
            else              __stcs(o2 + (g9 + i - 256), buf[512 + (i - 256)]);
        }
    }
}

__global__ void __launch_bounds__(TPB)
tp_kernel_split2(const float* __restrict__ x0f, const float* __restrict__ y0f,
                 const float* __restrict__ x1f, const float* __restrict__ y1f,
                 const float* __restrict__ x2f, const float* __restrict__ y2f,
                 float* __restrict__ o0f, float* __restrict__ o1f, float* __restrict__ o2f,
                 int total)
{
    __shared__ float4 sbuf[2 * BUF_F4];   // 53,248 B -> 4 CTAs/SM

    const int tid = threadIdx.x;
    const int P0 = blockIdx.x * (2 * PT);

    const float4* x0 = reinterpret_cast<const float4*>(x0f);
    const float4* y0 = reinterpret_cast<const float4*>(y0f);
    const float4* x1 = reinterpret_cast<const float4*>(x1f);
    const float4* y1 = reinterpret_cast<const float4*>(y1f);
    const float4* x2 = reinterpret_cast<const float4*>(x2f);
    const float4* y2 = reinterpret_cast<const float4*>(y2f);
    float4* o0 = reinterpret_cast<float4*>(o0f);
    float4* o1 = reinterpret_cast<float4*>(o1f);
    float4* o2 = reinterpret_cast<float4*>(o2f);

    if (P0 + 2 * PT <= total) {
        // ================= fast path: two full half-tiles =================
        const int g0 = P0 >> 2;          // f4 index of half 0
        const int g1 = g0 + (PT >> 2);   // f4 index of half 1

        stage_half(sbuf, g0, tid, x0, y0, x1, y1, x2, y2);
        asm volatile("cp.async.commit_group;");
        stage_half(sbuf + BUF_F4, g1, tid, x0, y0, x1, y1, x2, y2);
        asm volatile("cp.async.commit_group;");

        // half 0: compute+store while half 1 still in flight
        asm volatile("cp.async.wait_group 1;");
        __syncthreads();
        compute_half(sbuf, tid);
        __syncthreads();
        store_half(sbuf, g0, tid, o0, o1, o2);

        // half 1
        asm volatile("cp.async.wait_group 0;");
        __syncthreads();
        compute_half(sbuf + BUF_F4, tid);
        __syncthreads();
        store_half(sbuf + BUF_F4, g1, tid, o0, o1, o2);
    } else {
        // ================= tail path: scalar with guards =================
        for (int h = 0; h < 2; ++h) {
            int p = P0 + h * PT + tid;
            if (p < total) {
                float a = x0f[p], b = y0f[p];
                float u[3], v[3], A[9], B[9];
#pragma unroll
                for (int i = 0; i < 3; ++i) { u[i] = x1f[p * 3 + i]; v[i] = y1f[p * 3 + i]; }
#pragma unroll
                for (int i = 0; i < 9; ++i) { A[i] = x2f[p * 9 + i]; B[i] = y2f[p * 9 + i]; }
                float r0, r1[3], r2[9];
                tp_pair(a, b, u, v, A, B, &r0, r1, r2);
                o0f[p] = r0;
#pragma unroll
                for (int i = 0; i < 3; ++i) o1f[p * 3 + i] = r1[i];
#pragma unroll
                for (int i = 0; i < 9; ++i) o2f[p * 9 + i] = r2[i];
            }
        }
    }
}

extern "C" void kernel_launch(void* const* d_in, const int* in_sizes, int n_in,
                              void* d_out, int out_size)
{
    // Resolve inputs by element count: s = base (rank-0), 3s (rank-1), 9s (rank-2).
    // First occurrence of a size = x tensor, second = y tensor (robust to both
    // metadata orderings).
    int s = in_sizes[0];
    for (int i = 1; i < n_in; ++i) if (in_sizes[i] < s) s = in_sizes[i];

    const float* X[3] = {nullptr, nullptr, nullptr};
    const float* Y[3] = {nullptr, nullptr, nullptr};
    for (int i = 0; i < n_in; ++i) {
        int r;
        if (in_sizes[i] == s)          r = 0;
        else if (in_sizes[i] == 3 * s) r = 1;
        else                           r = 2;
        if (X[r] == nullptr) X[r] = (const float*)d_in[i];
        else                 Y[r] = (const float*)d_in[i];
    }

    float* o0 = (float*)d_out;       // s elements
    float* o1 = o0 + (size_t)s;      // 3s elements
    float* o2 = o0 + (size_t)4 * s;  // 9s elements

    int blocks = (s + 2 * PT - 1) / (2 * PT);
    tp_kernel_split2<<<blocks, TPB>>>(X[0], Y[0], X[1], Y[1], X[2], Y[2],
                                      o0, o1, o2, s);
}